// round 14
// baseline (speedup 1.0000x reference)
#include <cuda_runtime.h>
#include <cstdint>

#define NN 100000
#define NE 600000
#define DIMV 128
#define NLAYERS 4
#define NG 1000
#define ED 512
#define BNEPS 1e-4f

// ---------------- scratch (static device allocations; no cudaMalloc) --------
__device__ __align__(16) float g_h[(size_t)NN * DIMV];
__device__ __align__(16) float g_agg[(size_t)NN * DIMV];   // reused as h2
__device__ __align__(16) float g_t[(size_t)NN * DIMV];
__device__ __align__(16) float g_colsum[2 * DIMV];
__device__ __align__(16) float g_y[(size_t)NG * ED];
__device__ __align__(16) float g_fa[(size_t)NG * ED];
__device__ __align__(16) float g_fb[(size_t)NG * ED];

__device__ __forceinline__ float lrelu_f(float v) { return v > 0.f ? v : 0.01f * v; }

__global__ void zero_y_kernel() {
    int i = blockIdx.x * blockDim.x + threadIdx.x;   // 128000 float4
    ((float4*)g_y)[i] = make_float4(0.f, 0.f, 0.f, 0.f);
}

// ================= mma.sync tf32 node GEMM, double-buffered pipeline ========
// C[M,128] = op(A(+A2)) @ W[128,128], 3-term TF32 split (hi/lo).
// Block tile 128x128, 8 warps (2 row-groups x 4 col-groups), warp tile 64x32.
// K in 8 chunks of 16, double-buffered smem; per iteration: LDG(next) ->
// MMA(cur) -> cvt+STS(next) -> sync. Tiles: Ahi/Alo [128][20], Bhi/Blo [16][136]
// (fragment LDS conflict-free: (qr*20+qc) and (qc*136+qr) mod 32 all distinct).

#define BK 16
#define APAD 20
#define BPAD 136
#define A_TILE (128 * APAD)           // floats
#define B_TILE (BK * BPAD)            // floats
#define BUF_FLOATS (2 * A_TILE + 2 * B_TILE)      // 9472 floats = 37888 B
#define SMEM_MMA (2 * BUF_FLOATS * 4)             // 75776 B

__device__ __forceinline__ uint32_t tf32_hi(float x) {
    uint32_t y; asm("cvt.rna.tf32.f32 %0, %1;" : "=r"(y) : "f"(x)); return y;
}
__device__ __forceinline__ void mma8(float* d, const uint32_t* a, const uint32_t* b) {
    asm volatile(
        "mma.sync.aligned.m16n8k8.row.col.f32.tf32.tf32.f32 "
        "{%0,%1,%2,%3}, {%4,%5,%6,%7}, {%8,%9}, {%0,%1,%2,%3};"
        : "+f"(d[0]), "+f"(d[1]), "+f"(d[2]), "+f"(d[3])
        : "r"(a[0]), "r"(a[1]), "r"(a[2]), "r"(a[3]), "r"(b[0]), "r"(b[1]));
}

template<bool ADD2, bool LRELU, bool COLSUM, bool BIAS>
__global__ void __launch_bounds__(256, 2)
gemm_node_mma(const float* __restrict__ A, const float* __restrict__ A2,
              const float* __restrict__ W, const float* __restrict__ bias,
              float* __restrict__ C, int M)
{
    extern __shared__ float smem[];
    __shared__ float scol[2 * DIMV];

    const int tid = threadIdx.x;
    const int warp = tid >> 5;
    const int lane = tid & 31;
    const int qr = lane >> 2;       // 0..7
    const int qc = lane & 3;        // 0..3
    const int wr = warp & 1;        // row group (64 rows)
    const int wc = warp >> 1;       // col group (32 cols)
    const int rowBase = blockIdx.x * 128;

    // fill indices (it in {0,1} adds +64 rows for A, +8 k-rows for B)
    const int r0 = tid >> 2;              // 0..63
    const int c4 = (tid & 3) * 4;         // 0,4,8,12
    const int kr0 = tid >> 5;             // 0..7
    const int n4 = (tid & 31) * 4;        // 0..124

    if (COLSUM) scol[tid] = 0.f;

    float acc[4][4][4];
#pragma unroll
    for (int mf = 0; mf < 4; mf++)
#pragma unroll
        for (int nf = 0; nf < 4; nf++)
#pragma unroll
            for (int e = 0; e < 4; e++) acc[mf][nf][e] = 0.f;

    float4 aR[2], a2R[2], bR[2];
    const float4 z4 = make_float4(0.f, 0.f, 0.f, 0.f);

    // ---- load chunk kc's global data into registers ----
    auto loadregs = [&](int kc) {
        const int k0 = kc * BK;
        const int gr0 = rowBase + r0;
#pragma unroll
        for (int it = 0; it < 2; it++) {
            int gr = gr0 + it * 64;
            aR[it] = (gr < M) ? *(const float4*)(A + (size_t)gr * DIMV + k0 + c4) : z4;
            if (ADD2)
                a2R[it] = (gr < M) ? *(const float4*)(A2 + (size_t)gr * DIMV + k0 + c4) : z4;
            bR[it] = *(const float4*)(W + (size_t)(k0 + kr0 + it * 8) * DIMV + n4);
        }
    };

    // ---- cvt + STS registers into buffer b ----
    auto store = [&](int b) {
        float* Ahi = smem + (size_t)b * BUF_FLOATS;
        float* Alo = Ahi + A_TILE;
        float* Bhi = Alo + A_TILE;
        float* Blo = Bhi + B_TILE;
#pragma unroll
        for (int it = 0; it < 2; it++) {
            float4 v = aR[it];
            if (ADD2) {
                v.x += a2R[it].x; v.y += a2R[it].y; v.z += a2R[it].z; v.w += a2R[it].w;
            }
            float4 hi, lo;
            hi.x = __uint_as_float(tf32_hi(v.x)); lo.x = __uint_as_float(tf32_hi(v.x - hi.x));
            hi.y = __uint_as_float(tf32_hi(v.y)); lo.y = __uint_as_float(tf32_hi(v.y - hi.y));
            hi.z = __uint_as_float(tf32_hi(v.z)); lo.z = __uint_as_float(tf32_hi(v.z - hi.z));
            hi.w = __uint_as_float(tf32_hi(v.w)); lo.w = __uint_as_float(tf32_hi(v.w - hi.w));
            int off = (r0 + it * 64) * APAD + c4;
            *(float4*)(Ahi + off) = hi;
            *(float4*)(Alo + off) = lo;

            float4 bv = bR[it];
            float4 bh, bl;
            bh.x = __uint_as_float(tf32_hi(bv.x)); bl.x = __uint_as_float(tf32_hi(bv.x - bh.x));
            bh.y = __uint_as_float(tf32_hi(bv.y)); bl.y = __uint_as_float(tf32_hi(bv.y - bh.y));
            bh.z = __uint_as_float(tf32_hi(bv.z)); bl.z = __uint_as_float(tf32_hi(bv.z - bh.z));
            bh.w = __uint_as_float(tf32_hi(bv.w)); bl.w = __uint_as_float(tf32_hi(bv.w - bh.w));
            int boff = (kr0 + it * 8) * BPAD + n4;
            *(float4*)(Bhi + boff) = bh;
            *(float4*)(Blo + boff) = bl;
        }
    };

    // ---- MMA on buffer b ----
    auto domma = [&](int b) {
        const float* Ahi = smem + (size_t)b * BUF_FLOATS;
        const float* Alo = Ahi + A_TILE;
        const float* Bhi = Alo + A_TILE;
        const float* Blo = Bhi + B_TILE;
#pragma unroll
        for (int ks = 0; ks < 2; ks++) {
            const int kk = ks * 8 + qc;
            uint32_t bh[4][2], bl[4][2];
#pragma unroll
            for (int nf = 0; nf < 4; nf++) {
                int n = wc * 32 + nf * 8 + qr;
                bh[nf][0] = __float_as_uint(Bhi[kk * BPAD + n]);
                bh[nf][1] = __float_as_uint(Bhi[(kk + 4) * BPAD + n]);
                bl[nf][0] = __float_as_uint(Blo[kk * BPAD + n]);
                bl[nf][1] = __float_as_uint(Blo[(kk + 4) * BPAD + n]);
            }
#pragma unroll
            for (int mf = 0; mf < 4; mf++) {
                int R = wr * 64 + mf * 16 + qr;
                uint32_t ah[4], al[4];
                ah[0] = __float_as_uint(Ahi[R * APAD + kk]);
                ah[1] = __float_as_uint(Ahi[(R + 8) * APAD + kk]);
                ah[2] = __float_as_uint(Ahi[R * APAD + kk + 4]);
                ah[3] = __float_as_uint(Ahi[(R + 8) * APAD + kk + 4]);
                al[0] = __float_as_uint(Alo[R * APAD + kk]);
                al[1] = __float_as_uint(Alo[(R + 8) * APAD + kk]);
                al[2] = __float_as_uint(Alo[R * APAD + kk + 4]);
                al[3] = __float_as_uint(Alo[(R + 8) * APAD + kk + 4]);
#pragma unroll
                for (int nf = 0; nf < 4; nf++) {
                    mma8(acc[mf][nf], ah, bh[nf]);
                    mma8(acc[mf][nf], ah, bl[nf]);
                    mma8(acc[mf][nf], al, bh[nf]);
                }
            }
        }
    };

    // ---- pipelined mainloop over 8 K-chunks ----
    loadregs(0);
    store(0);
    __syncthreads();
#pragma unroll
    for (int kc = 0; kc < 8; kc++) {
        if (kc < 7) loadregs(kc + 1);     // LDGs issue; latency hidden by MMA
        domma(kc & 1);
        if (kc < 7) store((kc + 1) & 1);  // writes the buffer NOT in use
        __syncthreads();
    }

    // ---------------- epilogue ----------------
    // acc[mf][nf] = {(R,C),(R,C+1),(R+8,C),(R+8,C+1)}  R = wr*64+mf*16+qr,
    // C = wc*32 + nf*8 + 2*qc.
    float cse[4], cso[4], cqe[4], cqo[4];
#pragma unroll
    for (int nf = 0; nf < 4; nf++) { cse[nf] = cso[nf] = cqe[nf] = cqo[nf] = 0.f; }

#pragma unroll
    for (int mf = 0; mf < 4; mf++) {
        int R = wr * 64 + mf * 16 + qr;
#pragma unroll
        for (int nf = 0; nf < 4; nf++) {
            int Ccol = wc * 32 + nf * 8 + 2 * qc;
            float d0 = acc[mf][nf][0], d1 = acc[mf][nf][1];
            float d2 = acc[mf][nf][2], d3 = acc[mf][nf][3];
            if (BIAS) {
                float b0 = __ldg(bias + Ccol), b1 = __ldg(bias + Ccol + 1);
                d0 += b0; d1 += b1; d2 += b0; d3 += b1;
            }
            if (LRELU) { d0 = lrelu_f(d0); d1 = lrelu_f(d1); d2 = lrelu_f(d2); d3 = lrelu_f(d3); }
            if (COLSUM) {
                // invalid rows contribute 0 (A zero-filled, no bias/lrelu in COLSUM use)
                cse[nf] += d0 + d2;             cso[nf] += d1 + d3;
                cqe[nf] += d0 * d0 + d2 * d2;   cqo[nf] += d1 * d1 + d3 * d3;
            }
            int g0 = rowBase + R;
            int g1 = g0 + 8;
            if (g0 < M) *(float2*)(C + (size_t)g0 * DIMV + Ccol) = make_float2(d0, d1);
            if (g1 < M) *(float2*)(C + (size_t)g1 * DIMV + Ccol) = make_float2(d2, d3);
        }
    }
    if (COLSUM) {
#pragma unroll
        for (int nf = 0; nf < 4; nf++) {
            float s0 = cse[nf], s1 = cso[nf], q0 = cqe[nf], q1 = cqo[nf];
#pragma unroll
            for (int o = 4; o < 32; o <<= 1) {
                s0 += __shfl_xor_sync(0xffffffffu, s0, o);
                s1 += __shfl_xor_sync(0xffffffffu, s1, o);
                q0 += __shfl_xor_sync(0xffffffffu, q0, o);
                q1 += __shfl_xor_sync(0xffffffffu, q1, o);
            }
            if (lane < 4) {
                int Ccol = wc * 32 + nf * 8 + 2 * qc;
                atomicAdd(&scol[Ccol], s0);
                atomicAdd(&scol[Ccol + 1], s1);
                atomicAdd(&scol[128 + Ccol], q0);
                atomicAdd(&scol[128 + Ccol + 1], q1);
            }
        }
        __syncthreads();
        atomicAdd(&g_colsum[tid], scol[tid]);
    }
}

// ---------------- edge scatter: agg[dst] += h[src], one warp per edge -------
__global__ void __launch_bounds__(256)
scatter_kernel(const int* __restrict__ ei, const float* __restrict__ h,
               float* __restrict__ agg)
{
    if (blockIdx.x == 0) g_colsum[threadIdx.x] = 0.f;

    int gid = blockIdx.x * blockDim.x + threadIdx.x;
    int e = gid >> 5;
    int lane = gid & 31;
    if (e >= NE) return;
    int s = __ldg(ei + e);
    int d = __ldg(ei + NE + e);
    float4 v = *(const float4*)(h + (size_t)s * DIMV + lane * 4);
    float* p = agg + (size_t)d * DIMV + lane * 4;
    asm volatile("red.global.add.v4.f32 [%0], {%1,%2,%3,%4};"
                 :: "l"(p), "f"(v.x), "f"(v.y), "f"(v.z), "f"(v.w) : "memory");
}

// ---------------- BatchNorm apply + global_add_pool + agg-rezero ------------
__global__ void __launch_bounds__(256)
bn_pool_kernel(float* __restrict__ h2, const int* __restrict__ batch,
               const float* __restrict__ bn_g, const float* __restrict__ bn_b,
               float* __restrict__ hout, int layer)
{
    int gid = blockIdx.x * blockDim.x + threadIdx.x;
    if (gid >= NN * 32) return;
    int row = gid >> 5;
    int c = (gid & 31) * 4;

    const float inv_n = 1.f / (float)NN;
    float4 s1 = *(const float4*)(g_colsum + c);
    float4 s2 = *(const float4*)(g_colsum + 128 + c);
    float4 mean = make_float4(s1.x * inv_n, s1.y * inv_n, s1.z * inv_n, s1.w * inv_n);
    float4 inv;
    inv.x = rsqrtf(s2.x * inv_n - mean.x * mean.x + BNEPS);
    inv.y = rsqrtf(s2.y * inv_n - mean.y * mean.y + BNEPS);
    inv.z = rsqrtf(s2.z * inv_n - mean.z * mean.z + BNEPS);
    inv.w = rsqrtf(s2.w * inv_n - mean.w * mean.w + BNEPS);
    float4 gg = *(const float4*)(bn_g + layer * DIMV + c);
    float4 bb = *(const float4*)(bn_b + layer * DIMV + c);

    float4 v = *(const float4*)(h2 + (size_t)row * DIMV + c);
    // re-zero agg (h2 aliases g_agg) for the next layer's scatter
    *(float4*)(h2 + (size_t)row * DIMV + c) = make_float4(0.f, 0.f, 0.f, 0.f);

    float4 o;
    o.x = (v.x - mean.x) * inv.x * gg.x + bb.x;
    o.y = (v.y - mean.y) * inv.y * gg.y + bb.y;
    o.z = (v.z - mean.z) * inv.z * gg.z + bb.z;
    o.w = (v.w - mean.w) * inv.w * gg.w + bb.w;
    *(float4*)(hout + (size_t)row * DIMV + c) = o;

    int g = __ldg(batch + row);
    float* p = g_y + (size_t)g * ED + layer * DIMV + c;
    asm volatile("red.global.add.v4.f32 [%0], {%1,%2,%3,%4};"
                 :: "l"(p), "f"(o.x), "f"(o.y), "f"(o.z), "f"(o.w) : "memory");
}

// ---------------- FF GEMM: C[M,N] = op(A[M,K] @ B[K,N]) (+ADD) --------------
template<bool LRELU, bool ADDC>
__global__ void __launch_bounds__(256)
gemm_ff(const float* __restrict__ A, const float* __restrict__ B,
        const float* __restrict__ ADDP, float* __restrict__ C,
        int M, int N, int K)
{
    __shared__ float As[16][64];
    __shared__ float Bs[16][64];
    const int tid = threadIdx.x;
    const int tx = tid & 15, ty = tid >> 4;
    const int rowBase = blockIdx.y * 64;
    const int colBase = blockIdx.x * 64;

    float acc[4][4];
#pragma unroll
    for (int i = 0; i < 4; i++)
#pragma unroll
        for (int j = 0; j < 4; j++) acc[i][j] = 0.f;

    for (int k0 = 0; k0 < K; k0 += 16) {
        {
            int r = tid >> 2;
            int cp = (tid & 3) * 4;
            int gr = rowBase + r;
            float4 v = make_float4(0.f, 0.f, 0.f, 0.f);
            if (gr < M) v = *(const float4*)(A + (size_t)gr * K + k0 + cp);
            As[cp + 0][r] = v.x; As[cp + 1][r] = v.y;
            As[cp + 2][r] = v.z; As[cp + 3][r] = v.w;
        }
        {
            int r = tid >> 4;
            int cp = (tid & 15) * 4;
            *(float4*)&Bs[r][cp] = *(const float4*)(B + (size_t)(k0 + r) * N + colBase + cp);
        }
        __syncthreads();
#pragma unroll
        for (int k = 0; k < 16; k++) {
            float a[4], b[4];
            *(float4*)a = *(float4*)&As[k][ty * 4];
            *(float4*)b = *(float4*)&Bs[k][tx * 4];
#pragma unroll
            for (int i = 0; i < 4; i++)
#pragma unroll
                for (int j = 0; j < 4; j++)
                    acc[i][j] = fmaf(a[i], b[j], acc[i][j]);
        }
        __syncthreads();
    }

#pragma unroll
    for (int i = 0; i < 4; i++) {
        int gr = rowBase + ty * 4 + i;
        if (gr >= M) continue;
        float out[4];
#pragma unroll
        for (int j = 0; j < 4; j++) {
            float v = acc[i][j];
            if (LRELU) v = lrelu_f(v);
            out[j] = v;
        }
        if (ADDC) {
            float4 w = *(const float4*)(ADDP + (size_t)gr * N + colBase + tx * 4);
            out[0] += w.x; out[1] += w.y; out[2] += w.z; out[3] += w.w;
        }
        *(float4*)(C + (size_t)gr * N + colBase + tx * 4) = *(float4*)out;
    }
}

// ---------------- driver -----------------------------------------------------
extern "C" void kernel_launch(void* const* d_in, const int* in_sizes, int n_in,
                              void* d_out, int out_size)
{
    const float* x     = (const float*)d_in[0];
    const int*   ei    = (const int*)d_in[1];
    const int*   batch = (const int*)d_in[2];
    const float* pre_w = (const float*)d_in[3];
    const float* pre_b = (const float*)d_in[4];
    const float* cw1   = (const float*)d_in[5];
    const float* cw2   = (const float*)d_in[6];
    const float* bn_g  = (const float*)d_in[7];
    const float* bn_b  = (const float*)d_in[8];
    const float* ffw1  = (const float*)d_in[9];
    const float* ffw2  = (const float*)d_in[10];
    const float* ffw3  = (const float*)d_in[11];
    const float* ffsc  = (const float*)d_in[12];
    float*       out   = (float*)d_out;

    float *ph, *pagg, *pt, *py, *pfa, *pfb;
    cudaGetSymbolAddress((void**)&ph,   g_h);
    cudaGetSymbolAddress((void**)&pagg, g_agg);
    cudaGetSymbolAddress((void**)&pt,   g_t);
    cudaGetSymbolAddress((void**)&py,   g_y);
    cudaGetSymbolAddress((void**)&pfa,  g_fa);
    cudaGetSymbolAddress((void**)&pfb,  g_fb);

    cudaFuncSetAttribute(gemm_node_mma<false, false, false, true>,
                         cudaFuncAttributeMaxDynamicSharedMemorySize, SMEM_MMA);
    cudaFuncSetAttribute(gemm_node_mma<true, true, false, false>,
                         cudaFuncAttributeMaxDynamicSharedMemorySize, SMEM_MMA);
    cudaFuncSetAttribute(gemm_node_mma<false, false, true, false>,
                         cudaFuncAttributeMaxDynamicSharedMemorySize, SMEM_MMA);

    const int gemmBlocks = (NN + 127) / 128;            // 782
    const int scatBlocks = (NE * 32 + 255) / 256;       // 75000
    const int bnBlocks   = (NN * 32 + 255) / 256;       // 12500

    zero_y_kernel<<<(NG * ED / 4 + 255) / 256, 256>>>();

    // pre: h = x @ pre_w + pre_b
    gemm_node_mma<false, false, false, true><<<gemmBlocks, 256, SMEM_MMA>>>(
        x, nullptr, pre_w, pre_b, ph, NN);

    for (int l = 0; l < NLAYERS; l++) {
        // agg is zero here: zero-initialized statics on first call,
        // re-zeroed by bn_pool afterwards.
        scatter_kernel<<<scatBlocks, 256>>>(ei, ph, pagg);
        // t = lrelu((h + agg) @ W1)
        gemm_node_mma<true, true, false, false><<<gemmBlocks, 256, SMEM_MMA>>>(
            ph, pagg, cw1 + (size_t)l * DIMV * DIMV, nullptr, pt, NN);
        // h2 = t @ W2 (into agg), fused column sum/sumsq for BN
        gemm_node_mma<false, false, true, false><<<gemmBlocks, 256, SMEM_MMA>>>(
            pt, nullptr, cw2 + (size_t)l * DIMV * DIMV, nullptr, pagg, NN);
        // h = BN(h2); pooled[batch] += h; agg := 0
        bn_pool_kernel<<<bnBlocks, 256>>>(pagg, batch, bn_g, bn_b, ph, l);
    }

    dim3 gff(ED / 64, (NG + 63) / 64);
    gemm_ff<true,  false><<<gff, 256>>>(py,  ffw1, nullptr, pfa, NG, ED, ED);
    gemm_ff<true,  false><<<gff, 256>>>(pfa, ffw2, nullptr, pfb, NG, ED, ED);
    gemm_ff<true,  false><<<gff, 256>>>(pfb, ffw3, nullptr, pfa, NG, ED, ED);
    gemm_ff<false, true ><<<gff, 256>>>(py,  ffsc, pfa,     out, NG, ED, ED);
}

// round 17
// speedup vs baseline: 1.0596x; 1.0596x over previous
#include <cuda_runtime.h>
#include <cstdint>

#define NN 100000
#define NE 600000
#define DIMV 128
#define NLAYERS 4
#define NG 1000
#define ED 512
#define BNEPS 1e-4f

// ---------------- scratch (static device allocations; no cudaMalloc) --------
__device__ __align__(16) float g_h[(size_t)NN * DIMV];
__device__ __align__(16) float g_agg[(size_t)NN * DIMV];   // reused as h2
__device__ __align__(16) float g_t[(size_t)NN * DIMV];
__device__ __align__(16) float g_colsum[2 * DIMV];
__device__ __align__(16) float g_y[(size_t)NG * ED];
__device__ __align__(16) float g_fa[(size_t)NG * ED];
__device__ __align__(16) float g_fb[(size_t)NG * ED];

__device__ __forceinline__ float lrelu_f(float v) { return v > 0.f ? v : 0.01f * v; }

__global__ void zero_y_kernel() {
    int i = blockIdx.x * blockDim.x + threadIdx.x;   // 128000 float4
    ((float4*)g_y)[i] = make_float4(0.f, 0.f, 0.f, 0.f);
}

// ============ mma.sync tf32 node GEMM: cp.async raw tiles + reg-split =======
// C[M,128] = op(A(+A2)) @ W[128,128], 3-term TF32 split done at FRAGMENT load.
// Block tile 128x128, 8 warps (2x4), warp tile 64x32. K in 4 chunks of 32,
// double-buffered raw fp32 smem tiles filled by cp.async (no fill-phase
// cvt/STS). A raw [128][36], B raw [32][136]; frag LDS conflict-free
// (qr*4+qc and qc*8+qr mod 32 distinct), pitches 16B-aligned for cp.async.

#define BK 32
#define ARPAD 36
#define BRPAD 136
#define ABUF (128 * ARPAD)           // 4608 floats
#define BBUF (BK * BRPAD)            // 4352 floats
#define SMEM_MMA_1A (2 * (ABUF + BBUF) * 4)            // 71680 B
#define SMEM_MMA_2A (2 * (2 * ABUF + BBUF) * 4)        // 108544 B

__device__ __forceinline__ uint32_t tf32_hi(float x) {
    uint32_t y; asm("cvt.rna.tf32.f32 %0, %1;" : "=r"(y) : "f"(x)); return y;
}
__device__ __forceinline__ void mma8(float* d, const uint32_t* a, const uint32_t* b) {
    asm volatile(
        "mma.sync.aligned.m16n8k8.row.col.f32.tf32.tf32.f32 "
        "{%0,%1,%2,%3}, {%4,%5,%6,%7}, {%8,%9}, {%0,%1,%2,%3};"
        : "+f"(d[0]), "+f"(d[1]), "+f"(d[2]), "+f"(d[3])
        : "r"(a[0]), "r"(a[1]), "r"(a[2]), "r"(a[3]), "r"(b[0]), "r"(b[1]));
}
__device__ __forceinline__ void cp16(uint32_t dst, const float* src, uint32_t sz) {
    asm volatile("cp.async.cg.shared.global [%0], [%1], 16, %2;"
                 :: "r"(dst), "l"(src), "r"(sz) : "memory");
}
__device__ __forceinline__ uint32_t smem_u32(const void* p) {
    uint32_t a;
    asm("{ .reg .u64 t; cvta.to.shared.u64 t, %1; cvt.u32.u64 %0, t; }" : "=r"(a) : "l"(p));
    return a;
}

template<bool ADD2, bool LRELU, bool COLSUM, bool BIAS>
__global__ void __launch_bounds__(256, 2)
gemm_node_mma(const float* __restrict__ A, const float* __restrict__ A2,
              const float* __restrict__ W, const float* __restrict__ bias,
              float* __restrict__ C, int M)
{
    extern __shared__ float smem[];
    __shared__ float scol[2 * DIMV];

    constexpr int BUFF = (ADD2 ? 2 * ABUF : ABUF) + BBUF;   // floats per buffer
    constexpr int BOFF = (ADD2 ? 2 * ABUF : ABUF);          // B tile offset

    const int tid = threadIdx.x;
    const int warp = tid >> 5;
    const int lane = tid & 31;
    const int qr = lane >> 2;       // 0..7
    const int qc = lane & 3;        // 0..3
    const int wr = warp & 1;        // row group (64 rows)
    const int wc = warp >> 1;       // col group (32 cols)
    const int rowBase = blockIdx.x * 128;
    const uint32_t sbase = smem_u32(smem);

    if (COLSUM) scol[tid] = 0.f;

    float acc[4][4][4];
#pragma unroll
    for (int mf = 0; mf < 4; mf++)
#pragma unroll
        for (int nf = 0; nf < 4; nf++)
#pragma unroll
            for (int e = 0; e < 4; e++) acc[mf][nf][e] = 0.f;

    // ---- async-fill raw fp32 tiles for chunk kc into buffer b ----
    auto fill = [&](int kc, int b) {
        const int k0 = kc * BK;
        const uint32_t bb = sbase + (uint32_t)(b * BUFF) * 4u;
#pragma unroll
        for (int it = 0; it < 4; it++) {           // A: 128 rows x 32 floats
            int f = tid + it * 256;
            int r = f >> 3;
            int c4 = (f & 7) * 4;
            int gr = rowBase + r;
            uint32_t sz = (gr < M) ? 16u : 0u;
            int grc = gr < M ? gr : (M - 1);
            cp16(bb + (uint32_t)(r * ARPAD + c4) * 4u,
                 A + (size_t)grc * DIMV + k0 + c4, sz);
            if (ADD2)
                cp16(bb + (uint32_t)(ABUF + r * ARPAD + c4) * 4u,
                     A2 + (size_t)grc * DIMV + k0 + c4, sz);
        }
#pragma unroll
        for (int it = 0; it < 4; it++) {           // B: 32 k-rows x 128 floats
            int f = tid + it * 256;
            int kr = f >> 5;
            int n4 = (f & 31) * 4;
            cp16(bb + (uint32_t)(BOFF + kr * BRPAD + n4) * 4u,
                 W + (size_t)(k0 + kr) * DIMV + n4, 16u);
        }
        asm volatile("cp.async.commit_group;" ::: "memory");
    };

    // ---- MMA on buffer b: split hi/lo at fragment load ----
    auto domma = [&](int b) {
        const float* Araw = smem + (size_t)b * BUFF;
        const float* A2raw = Araw + ABUF;
        const float* Braw = Araw + BOFF;
#pragma unroll
        for (int ks = 0; ks < 4; ks++) {
            const int kk = ks * 8 + qc;
            uint32_t bh[4][2], bl[4][2];
#pragma unroll
            for (int nf = 0; nf < 4; nf++) {
                int n = wc * 32 + nf * 8 + qr;
                float b0 = Braw[kk * BRPAD + n];
                float b1 = Braw[(kk + 4) * BRPAD + n];
                bh[nf][0] = tf32_hi(b0);
                bl[nf][0] = tf32_hi(b0 - __uint_as_float(bh[nf][0]));
                bh[nf][1] = tf32_hi(b1);
                bl[nf][1] = tf32_hi(b1 - __uint_as_float(bh[nf][1]));
            }
#pragma unroll
            for (int mf = 0; mf < 4; mf++) {
                int R = wr * 64 + mf * 16 + qr;
                float av[4];
                av[0] = Araw[R * ARPAD + kk];
                av[1] = Araw[(R + 8) * ARPAD + kk];
                av[2] = Araw[R * ARPAD + kk + 4];
                av[3] = Araw[(R + 8) * ARPAD + kk + 4];
                if (ADD2) {
                    av[0] += A2raw[R * ARPAD + kk];
                    av[1] += A2raw[(R + 8) * ARPAD + kk];
                    av[2] += A2raw[R * ARPAD + kk + 4];
                    av[3] += A2raw[(R + 8) * ARPAD + kk + 4];
                }
                uint32_t ah[4], al[4];
#pragma unroll
                for (int i = 0; i < 4; i++) {
                    ah[i] = tf32_hi(av[i]);
                    al[i] = tf32_hi(av[i] - __uint_as_float(ah[i]));
                }
#pragma unroll
                for (int nf = 0; nf < 4; nf++) {
                    mma8(acc[mf][nf], ah, bh[nf]);
                    mma8(acc[mf][nf], ah, bl[nf]);
                    mma8(acc[mf][nf], al, bh[nf]);
                }
            }
        }
    };

    // ---- mainloop: 2-stage cp.async pipeline over 4 K-chunks ----
    fill(0, 0);
#pragma unroll
    for (int kc = 0; kc < 4; kc++) {
        asm volatile("cp.async.wait_group 0;" ::: "memory");
        __syncthreads();                       // publish fills; read-barrier for prev domma
        if (kc < 3) fill(kc + 1, (kc + 1) & 1);
        domma(kc & 1);
    }

    // ---------------- epilogue ----------------
    // acc[mf][nf] = {(R,C),(R,C+1),(R+8,C),(R+8,C+1)}  R = wr*64+mf*16+qr,
    // C = wc*32 + nf*8 + 2*qc.
    float cse[4], cso[4], cqe[4], cqo[4];
#pragma unroll
    for (int nf = 0; nf < 4; nf++) { cse[nf] = cso[nf] = cqe[nf] = cqo[nf] = 0.f; }

#pragma unroll
    for (int mf = 0; mf < 4; mf++) {
        int R = wr * 64 + mf * 16 + qr;
#pragma unroll
        for (int nf = 0; nf < 4; nf++) {
            int Ccol = wc * 32 + nf * 8 + 2 * qc;
            float d0 = acc[mf][nf][0], d1 = acc[mf][nf][1];
            float d2 = acc[mf][nf][2], d3 = acc[mf][nf][3];
            if (BIAS) {
                float b0 = __ldg(bias + Ccol), b1 = __ldg(bias + Ccol + 1);
                d0 += b0; d1 += b1; d2 += b0; d3 += b1;
            }
            if (LRELU) { d0 = lrelu_f(d0); d1 = lrelu_f(d1); d2 = lrelu_f(d2); d3 = lrelu_f(d3); }
            if (COLSUM) {
                cse[nf] += d0 + d2;             cso[nf] += d1 + d3;
                cqe[nf] += d0 * d0 + d2 * d2;   cqo[nf] += d1 * d1 + d3 * d3;
            }
            int g0 = rowBase + R;
            int g1 = g0 + 8;
            if (g0 < M) *(float2*)(C + (size_t)g0 * DIMV + Ccol) = make_float2(d0, d1);
            if (g1 < M) *(float2*)(C + (size_t)g1 * DIMV + Ccol) = make_float2(d2, d3);
        }
    }
    if (COLSUM) {
#pragma unroll
        for (int nf = 0; nf < 4; nf++) {
            float s0 = cse[nf], s1 = cso[nf], q0 = cqe[nf], q1 = cqo[nf];
#pragma unroll
            for (int o = 4; o < 32; o <<= 1) {
                s0 += __shfl_xor_sync(0xffffffffu, s0, o);
                s1 += __shfl_xor_sync(0xffffffffu, s1, o);
                q0 += __shfl_xor_sync(0xffffffffu, q0, o);
                q1 += __shfl_xor_sync(0xffffffffu, q1, o);
            }
            if (lane < 4) {
                int Ccol = wc * 32 + nf * 8 + 2 * qc;
                atomicAdd(&scol[Ccol], s0);
                atomicAdd(&scol[Ccol + 1], s1);
                atomicAdd(&scol[128 + Ccol], q0);
                atomicAdd(&scol[128 + Ccol + 1], q1);
            }
        }
        __syncthreads();
        atomicAdd(&g_colsum[tid], scol[tid]);
    }
}

// ---------------- edge scatter: agg[dst] += h[src], one warp per edge -------
__global__ void __launch_bounds__(256)
scatter_kernel(const int* __restrict__ ei, const float* __restrict__ h,
               float* __restrict__ agg)
{
    if (blockIdx.x == 0) g_colsum[threadIdx.x] = 0.f;

    int gid = blockIdx.x * blockDim.x + threadIdx.x;
    int e = gid >> 5;
    int lane = gid & 31;
    if (e >= NE) return;
    int s = __ldg(ei + e);
    int d = __ldg(ei + NE + e);
    float4 v = *(const float4*)(h + (size_t)s * DIMV + lane * 4);
    float* p = agg + (size_t)d * DIMV + lane * 4;
    asm volatile("red.global.add.v4.f32 [%0], {%1,%2,%3,%4};"
                 :: "l"(p), "f"(v.x), "f"(v.y), "f"(v.z), "f"(v.w) : "memory");
}

// ---------------- BatchNorm apply + global_add_pool + agg-rezero ------------
__global__ void __launch_bounds__(256)
bn_pool_kernel(float* __restrict__ h2, const int* __restrict__ batch,
               const float* __restrict__ bn_g, const float* __restrict__ bn_b,
               float* __restrict__ hout, int layer)
{
    int gid = blockIdx.x * blockDim.x + threadIdx.x;
    if (gid >= NN * 32) return;
    int row = gid >> 5;
    int c = (gid & 31) * 4;

    const float inv_n = 1.f / (float)NN;
    float4 s1 = *(const float4*)(g_colsum + c);
    float4 s2 = *(const float4*)(g_colsum + 128 + c);
    float4 mean = make_float4(s1.x * inv_n, s1.y * inv_n, s1.z * inv_n, s1.w * inv_n);
    float4 inv;
    inv.x = rsqrtf(s2.x * inv_n - mean.x * mean.x + BNEPS);
    inv.y = rsqrtf(s2.y * inv_n - mean.y * mean.y + BNEPS);
    inv.z = rsqrtf(s2.z * inv_n - mean.z * mean.z + BNEPS);
    inv.w = rsqrtf(s2.w * inv_n - mean.w * mean.w + BNEPS);
    float4 gg = *(const float4*)(bn_g + layer * DIMV + c);
    float4 bb = *(const float4*)(bn_b + layer * DIMV + c);

    float4 v = *(const float4*)(h2 + (size_t)row * DIMV + c);
    // re-zero agg (h2 aliases g_agg) for the next layer's scatter
    *(float4*)(h2 + (size_t)row * DIMV + c) = make_float4(0.f, 0.f, 0.f, 0.f);

    float4 o;
    o.x = (v.x - mean.x) * inv.x * gg.x + bb.x;
    o.y = (v.y - mean.y) * inv.y * gg.y + bb.y;
    o.z = (v.z - mean.z) * inv.z * gg.z + bb.z;
    o.w = (v.w - mean.w) * inv.w * gg.w + bb.w;
    *(float4*)(hout + (size_t)row * DIMV + c) = o;

    int g = __ldg(batch + row);
    float* p = g_y + (size_t)g * ED + layer * DIMV + c;
    asm volatile("red.global.add.v4.f32 [%0], {%1,%2,%3,%4};"
                 :: "l"(p), "f"(o.x), "f"(o.y), "f"(o.z), "f"(o.w) : "memory");
}

// ---------------- FF GEMM: C[M,N] = op(A[M,K] @ B[K,N]) (+ADD) --------------
template<bool LRELU, bool ADDC>
__global__ void __launch_bounds__(256)
gemm_ff(const float* __restrict__ A, const float* __restrict__ B,
        const float* __restrict__ ADDP, float* __restrict__ C,
        int M, int N, int K)
{
    __shared__ float As[16][64];
    __shared__ float Bs[16][64];
    const int tid = threadIdx.x;
    const int tx = tid & 15, ty = tid >> 4;
    const int rowBase = blockIdx.y * 64;
    const int colBase = blockIdx.x * 64;

    float acc[4][4];
#pragma unroll
    for (int i = 0; i < 4; i++)
#pragma unroll
        for (int j = 0; j < 4; j++) acc[i][j] = 0.f;

    for (int k0 = 0; k0 < K; k0 += 16) {
        {
            int r = tid >> 2;
            int cp = (tid & 3) * 4;
            int gr = rowBase + r;
            float4 v = make_float4(0.f, 0.f, 0.f, 0.f);
            if (gr < M) v = *(const float4*)(A + (size_t)gr * K + k0 + cp);
            As[cp + 0][r] = v.x; As[cp + 1][r] = v.y;
            As[cp + 2][r] = v.z; As[cp + 3][r] = v.w;
        }
        {
            int r = tid >> 4;
            int cp = (tid & 15) * 4;
            *(float4*)&Bs[r][cp] = *(const float4*)(B + (size_t)(k0 + r) * N + colBase + cp);
        }
        __syncthreads();
#pragma unroll
        for (int k = 0; k < 16; k++) {
            float a[4], b[4];
            *(float4*)a = *(float4*)&As[k][ty * 4];
            *(float4*)b = *(float4*)&Bs[k][tx * 4];
#pragma unroll
            for (int i = 0; i < 4; i++)
#pragma unroll
                for (int j = 0; j < 4; j++)
                    acc[i][j] = fmaf(a[i], b[j], acc[i][j]);
        }
        __syncthreads();
    }

#pragma unroll
    for (int i = 0; i < 4; i++) {
        int gr = rowBase + ty * 4 + i;
        if (gr >= M) continue;
        float out[4];
#pragma unroll
        for (int j = 0; j < 4; j++) {
            float v = acc[i][j];
            if (LRELU) v = lrelu_f(v);
            out[j] = v;
        }
        if (ADDC) {
            float4 w = *(const float4*)(ADDP + (size_t)gr * N + colBase + tx * 4);
            out[0] += w.x; out[1] += w.y; out[2] += w.z; out[3] += w.w;
        }
        *(float4*)(C + (size_t)gr * N + colBase + tx * 4) = *(float4*)out;
    }
}

// ---------------- driver -----------------------------------------------------
extern "C" void kernel_launch(void* const* d_in, const int* in_sizes, int n_in,
                              void* d_out, int out_size)
{
    const float* x     = (const float*)d_in[0];
    const int*   ei    = (const int*)d_in[1];
    const int*   batch = (const int*)d_in[2];
    const float* pre_w = (const float*)d_in[3];
    const float* pre_b = (const float*)d_in[4];
    const float* cw1   = (const float*)d_in[5];
    const float* cw2   = (const float*)d_in[6];
    const float* bn_g  = (const float*)d_in[7];
    const float* bn_b  = (const float*)d_in[8];
    const float* ffw1  = (const float*)d_in[9];
    const float* ffw2  = (const float*)d_in[10];
    const float* ffw3  = (const float*)d_in[11];
    const float* ffsc  = (const float*)d_in[12];
    float*       out   = (float*)d_out;

    float *ph, *pagg, *pt, *py, *pfa, *pfb;
    cudaGetSymbolAddress((void**)&ph,   g_h);
    cudaGetSymbolAddress((void**)&pagg, g_agg);
    cudaGetSymbolAddress((void**)&pt,   g_t);
    cudaGetSymbolAddress((void**)&py,   g_y);
    cudaGetSymbolAddress((void**)&pfa,  g_fa);
    cudaGetSymbolAddress((void**)&pfb,  g_fb);

    cudaFuncSetAttribute(gemm_node_mma<false, false, false, true>,
                         cudaFuncAttributeMaxDynamicSharedMemorySize, SMEM_MMA_1A);
    cudaFuncSetAttribute(gemm_node_mma<true, true, false, false>,
                         cudaFuncAttributeMaxDynamicSharedMemorySize, SMEM_MMA_2A);
    cudaFuncSetAttribute(gemm_node_mma<false, false, true, false>,
                         cudaFuncAttributeMaxDynamicSharedMemorySize, SMEM_MMA_1A);

    const int gemmBlocks = (NN + 127) / 128;            // 782
    const int scatBlocks = (NE * 32 + 255) / 256;       // 75000
    const int bnBlocks   = (NN * 32 + 255) / 256;       // 12500

    zero_y_kernel<<<(NG * ED / 4 + 255) / 256, 256>>>();

    // pre: h = x @ pre_w + pre_b
    gemm_node_mma<false, false, false, true><<<gemmBlocks, 256, SMEM_MMA_1A>>>(
        x, nullptr, pre_w, pre_b, ph, NN);

    for (int l = 0; l < NLAYERS; l++) {
        // agg is zero here: zero-initialized statics on first call,
        // re-zeroed by bn_pool afterwards.
        scatter_kernel<<<scatBlocks, 256>>>(ei, ph, pagg);
        // t = lrelu((h + agg) @ W1)
        gemm_node_mma<true, true, false, false><<<gemmBlocks, 256, SMEM_MMA_2A>>>(
            ph, pagg, cw1 + (size_t)l * DIMV * DIMV, nullptr, pt, NN);
        // h2 = t @ W2 (into agg), fused column sum/sumsq for BN
        gemm_node_mma<false, false, true, false><<<gemmBlocks, 256, SMEM_MMA_1A>>>(
            pt, nullptr, cw2 + (size_t)l * DIMV * DIMV, nullptr, pagg, NN);
        // h = BN(h2); pooled[batch] += h; agg := 0
        bn_pool_kernel<<<bnBlocks, 256>>>(pagg, batch, bn_g, bn_b, ph, l);
    }

    dim3 gff(ED / 64, (NG + 63) / 64);
    gemm_ff<true,  false><<<gff, 256>>>(py,  ffw1, nullptr, pfa, NG, ED, ED);
    gemm_ff<true,  false><<<gff, 256>>>(pfa, ffw2, nullptr, pfb, NG, ED, ED);
    gemm_ff<true,  false><<<gff, 256>>>(pfb, ffw3, nullptr, pfa, NG, ED, ED);
    gemm_ff<false, true ><<<gff, 256>>>(py,  ffsc, pfa,     out, NG, ED, ED);
}